// round 11
// baseline (speedup 1.0000x reference)
#include <cuda_runtime.h>
#include <cuda_fp16.h>
#include <cstdint>

// ============================================================================
// CourierEncoder fused MLP, sm_103 plain-target mma.sync FP16 path, round 11.
//   emb[B,384] -> h1 = lrelu(emb@w1+b1) -> out = lrelu(h1@w2+b2)
// fp16 operands (11-bit significand == tf32), fp32 accumulate, m16n8k16.
// PERSISTENT: grid = 296 CTAs (2/SM resident), each loops over row-blocks of
// 64 with strided assignment; params staged once; next block's xy/t
// prefetched into registers during gemm1 and committed to smem before sync2.
// Per block: 8 warps in 1(M64) x 8(N32) grid, warp tile 64x32, 64 accs/lane.
// A1/A2 separate packed fp16 smem buffers; fragment-native emb generation
// (thread-local STS.128); one LDS.128 per (mf,kstep); one LDG.128 per
// (nf,kstep-pair) from fragment-blocked gmem weights, fully unrolled.
// ============================================================================

static constexpr float NEG_SLOPEF = 0.01f;
static constexpr int KS1 = 24;   // 384/16 k-steps, layer 1
static constexpr int KS2 = 16;   // 256/16 k-steps, layer 2
static constexpr int SP1 = KS1 / 2;
static constexpr int SP2 = KS2 / 2;
static constexpr int NBLK = 4096;          // 262144 / 64
static constexpr int GRID = 296;           // 148 SMs * 2 resident CTAs

// fragment-blocked fp16 weights: [n8][sp][lane] uint4 = {b0(2sp),b1(2sp),b0(2sp+1),b1(2sp+1)}
__device__ uint4 g_w1B[32 * SP1 * 32];
__device__ uint4 g_w2B[32 * SP2 * 32];

// ---- smem layout (f32 words) ----
static constexpr int SM_A1   = 0;            // 3072 uint4 = 12288 words
static constexpr int SM_A2   = 12288;        // 2048 uint4 =  8192 words
static constexpr int SM_FR   = 20480;
static constexpr int SM_WT   = SM_FR + 512;
static constexpr int SM_BT   = SM_WT + 128;
static constexpr int SM_B1   = SM_BT + 128;
static constexpr int SM_B2   = SM_B1 + 256;
static constexpr int SM_X    = SM_B2 + 256;
static constexpr int SM_Y    = SM_X + 64;
static constexpr int SM_T    = SM_Y + 64;
static constexpr int SMEM_WORDS = SM_T + 64;
static constexpr int SMEM_BYTES = SMEM_WORDS * 4;   // ~86 KB -> 2 CTAs/SM

__device__ __forceinline__ float lrelu(float v) { return v >= 0.f ? v : NEG_SLOPEF * v; }

__device__ __forceinline__ void mma16(float* c, const uint32_t* a, uint32_t b0, uint32_t b1) {
    asm volatile(
        "mma.sync.aligned.m16n8k16.row.col.f32.f16.f16.f32 "
        "{%0,%1,%2,%3}, {%4,%5,%6,%7}, {%8,%9}, {%0,%1,%2,%3};"
        : "+f"(c[0]), "+f"(c[1]), "+f"(c[2]), "+f"(c[3])
        : "r"(a[0]), "r"(a[1]), "r"(a[2]), "r"(a[3]), "r"(b0), "r"(b1));
}

__device__ __forceinline__ uint32_t pack2(float lo, float hi) {
    __half2 h = __floats2half2_rn(lo, hi);
    return *(uint32_t*)&h;
}

// ---------------------------------------------------------------- prep kernel
__global__ void courier_prep(const float* __restrict__ w1, const float* __restrict__ w2) {
    int i = blockIdx.x * blockDim.x + threadIdx.x;
    if (i < 32 * SP1 * 32) {
        int n8 = i / (SP1 * 32);
        int rem = i % (SP1 * 32);
        int sp = rem >> 5, lane = rem & 31;
        int g = lane >> 2, tg = lane & 3;
        int n = n8 * 8 + g;
        int k0 = 32 * sp + 2 * tg;
        int k1 = k0 + 16;
        uint4 v;
        v.x = pack2(w1[(k0)      * 256 + n], w1[(k0 + 1)  * 256 + n]);
        v.y = pack2(w1[(k0 + 8)  * 256 + n], w1[(k0 + 9)  * 256 + n]);
        v.z = pack2(w1[(k1)      * 256 + n], w1[(k1 + 1)  * 256 + n]);
        v.w = pack2(w1[(k1 + 8)  * 256 + n], w1[(k1 + 9)  * 256 + n]);
        g_w1B[i] = v;
    }
    int j = i - 32 * SP1 * 32;
    if (j >= 0 && j < 32 * SP2 * 32) {
        int n8 = j / (SP2 * 32);
        int rem = j % (SP2 * 32);
        int sp = rem >> 5, lane = rem & 31;
        int g = lane >> 2, tg = lane & 3;
        int n = n8 * 8 + g;
        int k0 = 32 * sp + 2 * tg;
        int k1 = k0 + 16;
        uint4 v;
        v.x = pack2(w2[(k0)      * 256 + n], w2[(k0 + 1)  * 256 + n]);
        v.y = pack2(w2[(k0 + 8)  * 256 + n], w2[(k0 + 9)  * 256 + n]);
        v.z = pack2(w2[(k1)      * 256 + n], w2[(k1 + 1)  * 256 + n]);
        v.w = pack2(w2[(k1 + 8)  * 256 + n], w2[(k1 + 9)  * 256 + n]);
        g_w2B[j] = v;
    }
}

// ---------------------------------------------------------------- gemm core
template <int KS>
__device__ __forceinline__ void gemm_layer(const uint4* __restrict__ Wb,
                                           const uint4* __restrict__ smA4,
                                           int warp_n, int lane,
                                           float acc[4][4][4]) {
    constexpr int SP = KS / 2;
    const uint4* bptr[4];
#pragma unroll
    for (int nf = 0; nf < 4; nf++)
        bptr[nf] = Wb + (size_t)((warp_n * 4 + nf) * SP) * 32 + lane;

    uint4 bb[2][4];
#pragma unroll
    for (int nf = 0; nf < 4; nf++) bb[0][nf] = bptr[nf][0];

#pragma unroll
    for (int sp = 0; sp < SP; sp++) {
        const int cur = sp & 1;
        if (sp + 1 < SP) {
#pragma unroll
            for (int nf = 0; nf < 4; nf++)
                bb[cur ^ 1][nf] = bptr[nf][(sp + 1) * 32];
        }
#pragma unroll
        for (int h = 0; h < 2; h++) {
            const int s = 2 * sp + h;
            uint32_t a[4][4];
#pragma unroll
            for (int mf = 0; mf < 4; mf++) {
                uint4 av = smA4[(mf * KS + s) * 32 + lane];
                a[mf][0] = av.x; a[mf][1] = av.y; a[mf][2] = av.z; a[mf][3] = av.w;
            }
#pragma unroll
            for (int mf = 0; mf < 4; mf++)
#pragma unroll
                for (int nf = 0; nf < 4; nf++) {
                    uint32_t b0 = h ? bb[cur][nf].z : bb[cur][nf].x;
                    uint32_t b1 = h ? bb[cur][nf].w : bb[cur][nf].y;
                    mma16(acc[mf][nf], a[mf], b0, b1);
                }
        }
    }
}

// ---------------------------------------------------------------- main kernel
__global__ __launch_bounds__(256, 2)
void courier_main(const float* __restrict__ xy, const float* __restrict__ tin,
                  const float* __restrict__ w_sx, const float* __restrict__ b_sx,
                  const float* __restrict__ w_cx, const float* __restrict__ b_cx,
                  const float* __restrict__ w_sy, const float* __restrict__ b_sy,
                  const float* __restrict__ w_cy, const float* __restrict__ b_cy,
                  const float* __restrict__ w_t,  const float* __restrict__ b_t,
                  const float* __restrict__ b1,   const float* __restrict__ b2,
                  float* __restrict__ out) {
    extern __shared__ float sm[];
    uint4*  smA1 = (uint4*)(sm + SM_A1);
    uint4*  smA2 = (uint4*)(sm + SM_A2);
    float* sm_fr = sm + SM_FR;
    float* sm_wt = sm + SM_WT;
    float* sm_bt = sm + SM_BT;
    float* sm_b1 = sm + SM_B1;
    float* sm_b2 = sm + SM_B2;
    float* sm_x  = sm + SM_X;
    float* sm_y  = sm + SM_Y;
    float* sm_t  = sm + SM_T;

    const int tid    = threadIdx.x;
    const int lane   = tid & 31;
    const int warp_n = tid >> 5;          // 0..7

    // ---- stage params ONCE + first block's inputs ----
    if (tid < 128) {
        sm_wt[tid] = w_t[tid];
        sm_bt[tid] = b_t[tid];
    }
    if (tid < 64) {
        sm_fr[tid]       = w_sx[tid];  sm_fr[64 + tid]  = b_sx[tid];
        sm_fr[128 + tid] = w_cx[tid];  sm_fr[192 + tid] = b_cx[tid];
        sm_fr[256 + tid] = w_sy[tid];  sm_fr[320 + tid] = b_sy[tid];
        sm_fr[384 + tid] = w_cy[tid];  sm_fr[448 + tid] = b_cy[tid];
    }
    sm_b1[tid] = b1[tid];
    sm_b2[tid] = b2[tid];
    if (tid < 64) {
        int row = blockIdx.x * 64 + tid;
        float2 p = *(const float2*)(xy + 2 * row);
        sm_x[tid] = p.x;
        sm_y[tid] = p.y;
        sm_t[tid] = tin[row];
    }
    __syncthreads();

    const int mt = warp_n & 3;
    const int s0 = (warp_n >> 2) * 12;
    const int g = lane >> 2, tg = lane & 3;

    for (int blk = blockIdx.x; blk < NBLK; blk += GRID) {
        // ---- generate embedding A1 [64 x 384] FRAGMENT-NATIVE ----
        {
            const int r0 = mt * 16 + g, r1 = r0 + 8;
            const float xv0 = sm_x[r0], yv0 = sm_y[r0], tv0 = sm_t[r0];
            const float xv1 = sm_x[r1], yv1 = sm_y[r1], tv1 = sm_t[r1];

            auto embval = [&](int c, float xv, float yv, float tv) -> float {
                if (c < 64)  return __sinf(fmaf(xv, sm_fr[c], sm_fr[64 + c]));
                if (c < 128) { int i = c - 64;  return __cosf(fmaf(xv, sm_fr[128 + i], sm_fr[192 + i])); }
                if (c < 192) { int i = c - 128; return __sinf(fmaf(yv, sm_fr[256 + i], sm_fr[320 + i])); }
                if (c < 256) { int i = c - 192; return __cosf(fmaf(yv, sm_fr[384 + i], sm_fr[448 + i])); }
                int i = c - 256; return lrelu(fmaf(tv, sm_wt[i], sm_bt[i]));
            };

#pragma unroll
            for (int j = 0; j < 12; j++) {
                int s = s0 + j;
                int k0 = 16 * s + 2 * tg;
                uint4 st;
                st.x = pack2(embval(k0,     xv0, yv0, tv0), embval(k0 + 1, xv0, yv0, tv0));
                st.y = pack2(embval(k0,     xv1, yv1, tv1), embval(k0 + 1, xv1, yv1, tv1));
                st.z = pack2(embval(k0 + 8, xv0, yv0, tv0), embval(k0 + 9, xv0, yv0, tv0));
                st.w = pack2(embval(k0 + 8, xv1, yv1, tv1), embval(k0 + 9, xv1, yv1, tv1));
                smA1[(mt * KS1 + s) * 32 + lane] = st;
            }
        }
        __syncthreads();   // sync1: A1 ready; sm_x/y/t consumed

        // ---- prefetch next block's inputs into registers (hidden by gemm1) ----
        const int nblk_next = blk + GRID;
        float px = 0.f, py = 0.f, pt = 0.f;
        if (tid < 64 && nblk_next < NBLK) {
            int row = nblk_next * 64 + tid;
            float2 p = *(const float2*)(xy + 2 * row);
            px = p.x; py = p.y; pt = tin[row];
        }

        // ---- layer 1 ----
        float acc[4][4][4];
#pragma unroll
        for (int mf = 0; mf < 4; mf++)
#pragma unroll
            for (int nf = 0; nf < 4; nf++)
#pragma unroll
                for (int j = 0; j < 4; j++) acc[mf][nf][j] = 0.f;

        gemm_layer<KS1>(g_w1B, smA1, warp_n, lane, acc);

        // ---- epilogue 1: bias + lrelu + fp16 -> A2 ----
        {
#pragma unroll
            for (int mf = 0; mf < 4; mf++) {
#pragma unroll
                for (int e = 0; e < 2; e++) {
                    int col0 = warp_n * 32 + (2 * e) * 8 + 2 * tg;
                    int col1 = col0 + 8;
                    uint4 st;
                    st.x = pack2(lrelu(acc[mf][2*e][0]   + sm_b1[col0]),
                                 lrelu(acc[mf][2*e][1]   + sm_b1[col0 + 1]));
                    st.y = pack2(lrelu(acc[mf][2*e][2]   + sm_b1[col0]),
                                 lrelu(acc[mf][2*e][3]   + sm_b1[col0 + 1]));
                    st.z = pack2(lrelu(acc[mf][2*e+1][0] + sm_b1[col1]),
                                 lrelu(acc[mf][2*e+1][1] + sm_b1[col1 + 1]));
                    st.w = pack2(lrelu(acc[mf][2*e+1][2] + sm_b1[col1]),
                                 lrelu(acc[mf][2*e+1][3] + sm_b1[col1 + 1]));
                    int s2 = warp_n * 2 + e;
                    smA2[(mf * KS2 + s2) * 32 + lane] = st;
                }
            }
        }

        // ---- commit prefetched inputs (ordered by sync2 for next emb) ----
        if (tid < 64 && nblk_next < NBLK) {
            sm_x[tid] = px;
            sm_y[tid] = py;
            sm_t[tid] = pt;
        }
        __syncthreads();   // sync2: A2 ready + next inputs visible

        // ---- layer 2 ----
#pragma unroll
        for (int mf = 0; mf < 4; mf++)
#pragma unroll
            for (int nf = 0; nf < 4; nf++)
#pragma unroll
                for (int j = 0; j < 4; j++) acc[mf][nf][j] = 0.f;

        gemm_layer<KS2>(g_w2B, smA2, warp_n, lane, acc);

        // ---- final epilogue: bias + lrelu, float2 stores to gmem ----
        {
            float* obase = out + (size_t)blk * 64 * 256;
#pragma unroll
            for (int mf = 0; mf < 4; mf++) {
#pragma unroll
                for (int nf = 0; nf < 4; nf++) {
                    int row = mf * 16 + g;
                    int col = warp_n * 32 + nf * 8 + 2 * tg;
                    float2 v0, v1;
                    v0.x = lrelu(acc[mf][nf][0] + sm_b2[col]);
                    v0.y = lrelu(acc[mf][nf][1] + sm_b2[col + 1]);
                    v1.x = lrelu(acc[mf][nf][2] + sm_b2[col]);
                    v1.y = lrelu(acc[mf][nf][3] + sm_b2[col + 1]);
                    *(float2*)(obase + row * 256 + col)       = v0;
                    *(float2*)(obase + (row + 8) * 256 + col) = v1;
                }
            }
        }
        // loop: emb(i+1) writes A1 (all gemm1 readers passed sync2);
        // gemm2 stragglers read A2/sm_b2 only — disjoint. Safe without a
        // third barrier.
    }
}

// ---------------------------------------------------------------- launcher
extern "C" void kernel_launch(void* const* d_in, const int* in_sizes, int n_in,
                              void* d_out, int out_size) {
    const float* xy   = (const float*)d_in[0];
    const float* t    = (const float*)d_in[1];
    const float* w_sx = (const float*)d_in[2];
    const float* b_sx = (const float*)d_in[3];
    const float* w_cx = (const float*)d_in[4];
    const float* b_cx = (const float*)d_in[5];
    const float* w_sy = (const float*)d_in[6];
    const float* b_sy = (const float*)d_in[7];
    const float* w_cy = (const float*)d_in[8];
    const float* b_cy = (const float*)d_in[9];
    const float* w_t  = (const float*)d_in[10];
    const float* b_t  = (const float*)d_in[11];
    const float* w1   = (const float*)d_in[12];
    const float* b1   = (const float*)d_in[13];
    const float* w2   = (const float*)d_in[14];
    const float* b2   = (const float*)d_in[15];
    float* out = (float*)d_out;

    courier_prep<<<80, 256>>>(w1, w2);

    static bool attr_set = false;
    if (!attr_set) {
        cudaFuncSetAttribute(courier_main, cudaFuncAttributeMaxDynamicSharedMemorySize,
                             SMEM_BYTES);
        attr_set = true;
    }

    courier_main<<<GRID, 256, SMEM_BYTES>>>(xy, t, w_sx, b_sx, w_cx, b_cx,
                                            w_sy, b_sy, w_cy, b_cy,
                                            w_t, b_t, b1, b2, out);
}

// round 12
// speedup vs baseline: 1.1388x; 1.1388x over previous
#include <cuda_runtime.h>
#include <cuda_fp16.h>
#include <cstdint>

// ============================================================================
// CourierEncoder fused MLP, sm_103 plain-target mma.sync FP16 path, round 12.
//   emb[B,384] -> h1 = lrelu(emb@w1+b1) -> out = lrelu(h1@w2+b2)
// fp16 operands (11-bit significand == tf32), fp32 accumulate, m16n8k16.
// == R8 config (best: 234us) + layer-2 OUTPUT-COLUMN PERMUTATION ==
// CTA = 64 rows, 256 threads = 16 warps in 1(M64) x 8(N32) grid; 2 CTAs/SM.
// Warp tile 64x32: mf=4, nf=4, 64 accs/lane. Fragment-native emb (STS.128),
// LDS.128 A frags, LDG.128 fragment-blocked B.
// w2's columns are permuted in prep so each thread's 4 acc values per row are
// 4 CONSECUTIVE output columns -> final epilogue is aligned STG.128
// (16 instr/warp instead of 32 STG.64) -> final-store wavefronts halve.
// ============================================================================

static constexpr float NEG_SLOPEF = 0.01f;
static constexpr int KS1 = 24;   // 384/16 k-steps, layer 1
static constexpr int KS2 = 16;   // 256/16 k-steps, layer 2
static constexpr int SP1 = KS1 / 2;
static constexpr int SP2 = KS2 / 2;

// fragment-blocked fp16 weights: [n8][sp][lane] uint4 = {b0(2sp),b1(2sp),b0(2sp+1),b1(2sp+1)}
__device__ uint4 g_w1B[32 * SP1 * 32];
__device__ uint4 g_w2B[32 * SP2 * 32];

// ---- smem layout (f32 words) ----
static constexpr int SM_A1   = 0;            // 3072 uint4 = 12288 words
static constexpr int SM_A2   = 12288;        // 2048 uint4 =  8192 words
static constexpr int SM_FR   = 20480;
static constexpr int SM_WT   = SM_FR + 512;
static constexpr int SM_BT   = SM_WT + 128;
static constexpr int SM_B1   = SM_BT + 128;
static constexpr int SM_B2   = SM_B1 + 256;
static constexpr int SM_X    = SM_B2 + 256;
static constexpr int SM_Y    = SM_X + 64;
static constexpr int SM_T    = SM_Y + 64;
static constexpr int SMEM_WORDS = SM_T + 64;
static constexpr int SMEM_BYTES = SMEM_WORDS * 4;   // ~86 KB -> 2 CTAs/SM

__device__ __forceinline__ float lrelu(float v) { return v >= 0.f ? v : NEG_SLOPEF * v; }

__device__ __forceinline__ void mma16(float* c, const uint32_t* a, uint32_t b0, uint32_t b1) {
    asm volatile(
        "mma.sync.aligned.m16n8k16.row.col.f32.f16.f16.f32 "
        "{%0,%1,%2,%3}, {%4,%5,%6,%7}, {%8,%9}, {%0,%1,%2,%3};"
        : "+f"(c[0]), "+f"(c[1]), "+f"(c[2]), "+f"(c[3])
        : "r"(a[0]), "r"(a[1]), "r"(a[2]), "r"(a[3]), "r"(b0), "r"(b1));
}

__device__ __forceinline__ uint32_t pack2(float lo, float hi) {
    __half2 h = __floats2half2_rn(lo, hi);
    return *(uint32_t*)&h;
}

// ---------------------------------------------------------------- prep kernel
__global__ void courier_prep(const float* __restrict__ w1, const float* __restrict__ w2) {
    int i = blockIdx.x * blockDim.x + threadIdx.x;
    if (i < 32 * SP1 * 32) {
        int n8 = i / (SP1 * 32);
        int rem = i % (SP1 * 32);
        int sp = rem >> 5, lane = rem & 31;
        int g = lane >> 2, tg = lane & 3;
        int n = n8 * 8 + g;
        int k0 = 32 * sp + 2 * tg;
        int k1 = k0 + 16;
        uint4 v;
        v.x = pack2(w1[(k0)      * 256 + n], w1[(k0 + 1)  * 256 + n]);
        v.y = pack2(w1[(k0 + 8)  * 256 + n], w1[(k0 + 9)  * 256 + n]);
        v.z = pack2(w1[(k1)      * 256 + n], w1[(k1 + 1)  * 256 + n]);
        v.w = pack2(w1[(k1 + 8)  * 256 + n], w1[(k1 + 9)  * 256 + n]);
        g_w1B[i] = v;
    }
    int j = i - 32 * SP1 * 32;
    if (j >= 0 && j < 32 * SP2 * 32) {
        int n8 = j / (SP2 * 32);
        int rem = j % (SP2 * 32);
        int sp = rem >> 5, lane = rem & 31;
        int g = lane >> 2, tg = lane & 3;
        // Output-column permutation: frag n-slot g of tile nf=(2e+d) holds
        // actual column warpbase + 16e + 4*(g>>1) + 2d + (g&1), so D col j
        // = 2tg+h lands on consecutive columns per thread.
        int nf = n8 & 3;
        int e = nf >> 1, d = nf & 1;
        int n = (n8 >> 2) * 32 + e * 16 + 4 * (g >> 1) + 2 * d + (g & 1);
        int k0 = 32 * sp + 2 * tg;
        int k1 = k0 + 16;
        uint4 v;
        v.x = pack2(w2[(k0)      * 256 + n], w2[(k0 + 1)  * 256 + n]);
        v.y = pack2(w2[(k0 + 8)  * 256 + n], w2[(k0 + 9)  * 256 + n]);
        v.z = pack2(w2[(k1)      * 256 + n], w2[(k1 + 1)  * 256 + n]);
        v.w = pack2(w2[(k1 + 8)  * 256 + n], w2[(k1 + 9)  * 256 + n]);
        g_w2B[j] = v;
    }
}

// ---------------------------------------------------------------- gemm core
template <int KS>
__device__ __forceinline__ void gemm_layer(const uint4* __restrict__ Wb,
                                           const uint4* __restrict__ smA4,
                                           int warp_n, int lane,
                                           float acc[4][4][4]) {
    constexpr int SP = KS / 2;
    const uint4* bptr[4];
#pragma unroll
    for (int nf = 0; nf < 4; nf++)
        bptr[nf] = Wb + (size_t)((warp_n * 4 + nf) * SP) * 32 + lane;

    uint4 bb[2][4];
#pragma unroll
    for (int nf = 0; nf < 4; nf++) bb[0][nf] = bptr[nf][0];

#pragma unroll
    for (int sp = 0; sp < SP; sp++) {
        const int cur = sp & 1;
        if (sp + 1 < SP) {
#pragma unroll
            for (int nf = 0; nf < 4; nf++)
                bb[cur ^ 1][nf] = bptr[nf][(sp + 1) * 32];
        }
#pragma unroll
        for (int h = 0; h < 2; h++) {
            const int s = 2 * sp + h;
            uint32_t a[4][4];
#pragma unroll
            for (int mf = 0; mf < 4; mf++) {
                uint4 av = smA4[(mf * KS + s) * 32 + lane];
                a[mf][0] = av.x; a[mf][1] = av.y; a[mf][2] = av.z; a[mf][3] = av.w;
            }
#pragma unroll
            for (int mf = 0; mf < 4; mf++)
#pragma unroll
                for (int nf = 0; nf < 4; nf++) {
                    uint32_t b0 = h ? bb[cur][nf].z : bb[cur][nf].x;
                    uint32_t b1 = h ? bb[cur][nf].w : bb[cur][nf].y;
                    mma16(acc[mf][nf], a[mf], b0, b1);
                }
        }
    }
}

// ---------------------------------------------------------------- main kernel
__global__ __launch_bounds__(256, 2)
void courier_main(const float* __restrict__ xy, const float* __restrict__ tin,
                  const float* __restrict__ w_sx, const float* __restrict__ b_sx,
                  const float* __restrict__ w_cx, const float* __restrict__ b_cx,
                  const float* __restrict__ w_sy, const float* __restrict__ b_sy,
                  const float* __restrict__ w_cy, const float* __restrict__ b_cy,
                  const float* __restrict__ w_t,  const float* __restrict__ b_t,
                  const float* __restrict__ b1,   const float* __restrict__ b2,
                  float* __restrict__ out) {
    extern __shared__ float sm[];
    uint4*  smA1 = (uint4*)(sm + SM_A1);
    uint4*  smA2 = (uint4*)(sm + SM_A2);
    float* sm_fr = sm + SM_FR;
    float* sm_wt = sm + SM_WT;
    float* sm_bt = sm + SM_BT;
    float* sm_b1 = sm + SM_B1;
    float* sm_b2 = sm + SM_B2;
    float* sm_x  = sm + SM_X;
    float* sm_y  = sm + SM_Y;
    float* sm_t  = sm + SM_T;

    const int tid    = threadIdx.x;
    const int lane   = tid & 31;
    const int warp_n = tid >> 5;          // 0..7

    // ---- stage small params + per-row inputs ----
    if (tid < 64) {
        int row = blockIdx.x * 64 + tid;
        float2 p = *(const float2*)(xy + 2 * row);
        sm_x[tid] = p.x;
        sm_y[tid] = p.y;
        sm_t[tid] = tin[row];
    }
    if (tid < 128) {
        sm_wt[tid] = w_t[tid];
        sm_bt[tid] = b_t[tid];
    }
    if (tid < 64) {
        sm_fr[tid]       = w_sx[tid];  sm_fr[64 + tid]  = b_sx[tid];
        sm_fr[128 + tid] = w_cx[tid];  sm_fr[192 + tid] = b_cx[tid];
        sm_fr[256 + tid] = w_sy[tid];  sm_fr[320 + tid] = b_sy[tid];
        sm_fr[384 + tid] = w_cy[tid];  sm_fr[448 + tid] = b_cy[tid];
    }
    sm_b1[tid] = b1[tid];
    sm_b2[tid] = b2[tid];
    __syncthreads();

    // ---- generate embedding A1 [64 x 384] FRAGMENT-NATIVE ----
    // warp w owns mt = w&3, k-steps s0..s0+11 (s0 = (w>>2)*12).
    {
        const int mt = warp_n & 3;
        const int s0 = (warp_n >> 2) * 12;
        const int g = lane >> 2, tg = lane & 3;
        const int r0 = mt * 16 + g, r1 = r0 + 8;
        const float xv0 = sm_x[r0], yv0 = sm_y[r0], tv0 = sm_t[r0];
        const float xv1 = sm_x[r1], yv1 = sm_y[r1], tv1 = sm_t[r1];

        auto embval = [&](int c, float xv, float yv, float tv) -> float {
            if (c < 64)  return __sinf(fmaf(xv, sm_fr[c], sm_fr[64 + c]));
            if (c < 128) { int i = c - 64;  return __cosf(fmaf(xv, sm_fr[128 + i], sm_fr[192 + i])); }
            if (c < 192) { int i = c - 128; return __sinf(fmaf(yv, sm_fr[256 + i], sm_fr[320 + i])); }
            if (c < 256) { int i = c - 192; return __cosf(fmaf(yv, sm_fr[384 + i], sm_fr[448 + i])); }
            int i = c - 256; return lrelu(fmaf(tv, sm_wt[i], sm_bt[i]));
        };

#pragma unroll
        for (int j = 0; j < 12; j++) {
            int s = s0 + j;
            int k0 = 16 * s + 2 * tg;
            uint4 st;
            st.x = pack2(embval(k0,     xv0, yv0, tv0), embval(k0 + 1, xv0, yv0, tv0));
            st.y = pack2(embval(k0,     xv1, yv1, tv1), embval(k0 + 1, xv1, yv1, tv1));
            st.z = pack2(embval(k0 + 8, xv0, yv0, tv0), embval(k0 + 9, xv0, yv0, tv0));
            st.w = pack2(embval(k0 + 8, xv1, yv1, tv1), embval(k0 + 9, xv1, yv1, tv1));
            smA1[(mt * KS1 + s) * 32 + lane] = st;
        }
    }
    __syncthreads();

    // ---- layer 1 ----
    float acc[4][4][4];
#pragma unroll
    for (int mf = 0; mf < 4; mf++)
#pragma unroll
        for (int nf = 0; nf < 4; nf++)
#pragma unroll
            for (int j = 0; j < 4; j++) acc[mf][nf][j] = 0.f;

    gemm_layer<KS1>(g_w1B, smA1, warp_n, lane, acc);

    // ---- epilogue 1: bias + lrelu + fp16 -> A2 (separate buffer, no WAR sync) ----
    {
        const int tg = lane & 3;
#pragma unroll
        for (int mf = 0; mf < 4; mf++) {
#pragma unroll
            for (int e = 0; e < 2; e++) {
                int col0 = warp_n * 32 + (2 * e) * 8 + 2 * tg;
                int col1 = col0 + 8;
                uint4 st;
                st.x = pack2(lrelu(acc[mf][2*e][0]   + sm_b1[col0]),
                             lrelu(acc[mf][2*e][1]   + sm_b1[col0 + 1]));
                st.y = pack2(lrelu(acc[mf][2*e][2]   + sm_b1[col0]),
                             lrelu(acc[mf][2*e][3]   + sm_b1[col0 + 1]));
                st.z = pack2(lrelu(acc[mf][2*e+1][0] + sm_b1[col1]),
                             lrelu(acc[mf][2*e+1][1] + sm_b1[col1 + 1]));
                st.w = pack2(lrelu(acc[mf][2*e+1][2] + sm_b1[col1]),
                             lrelu(acc[mf][2*e+1][3] + sm_b1[col1 + 1]));
                int s2 = warp_n * 2 + e;
                smA2[(mf * KS2 + s2) * 32 + lane] = st;
            }
        }
    }
    __syncthreads();

    // ---- layer 2 (w2 columns permuted in prep) ----
#pragma unroll
    for (int mf = 0; mf < 4; mf++)
#pragma unroll
        for (int nf = 0; nf < 4; nf++)
#pragma unroll
            for (int j = 0; j < 4; j++) acc[mf][nf][j] = 0.f;

    gemm_layer<KS2>(g_w2B, smA2, warp_n, lane, acc);

    // ---- final epilogue: bias + lrelu, aligned STG.128 ----
    // With the permutation, thread (tg) holds for row r and pair e the actual
    // columns c..c+3 where c = warp_n*32 + e*16 + 4*tg:
    //   c+0 = acc[mf][2e][h0], c+1 = acc[mf][2e][h1],
    //   c+2 = acc[mf][2e+1][h0], c+3 = acc[mf][2e+1][h1]
    // (h0/h1 = elems {0,1} for row r0, {2,3} for row r1).
    {
        const int g  = lane >> 2;
        const int tg = lane & 3;
        float* obase = out + (size_t)blockIdx.x * 64 * 256;
#pragma unroll
        for (int mf = 0; mf < 4; mf++) {
            int r0 = mf * 16 + g;
#pragma unroll
            for (int e = 0; e < 2; e++) {
                int c = warp_n * 32 + e * 16 + 4 * tg;
                float4 v0, v1;
                v0.x = lrelu(acc[mf][2*e][0]   + sm_b2[c]);
                v0.y = lrelu(acc[mf][2*e][1]   + sm_b2[c + 1]);
                v0.z = lrelu(acc[mf][2*e+1][0] + sm_b2[c + 2]);
                v0.w = lrelu(acc[mf][2*e+1][1] + sm_b2[c + 3]);
                v1.x = lrelu(acc[mf][2*e][2]   + sm_b2[c]);
                v1.y = lrelu(acc[mf][2*e][3]   + sm_b2[c + 1]);
                v1.z = lrelu(acc[mf][2*e+1][2] + sm_b2[c + 2]);
                v1.w = lrelu(acc[mf][2*e+1][3] + sm_b2[c + 3]);
                *(float4*)(obase + r0 * 256 + c)       = v0;
                *(float4*)(obase + (r0 + 8) * 256 + c) = v1;
            }
        }
    }
}

// ---------------------------------------------------------------- launcher
extern "C" void kernel_launch(void* const* d_in, const int* in_sizes, int n_in,
                              void* d_out, int out_size) {
    const float* xy   = (const float*)d_in[0];
    const float* t    = (const float*)d_in[1];
    const float* w_sx = (const float*)d_in[2];
    const float* b_sx = (const float*)d_in[3];
    const float* w_cx = (const float*)d_in[4];
    const float* b_cx = (const float*)d_in[5];
    const float* w_sy = (const float*)d_in[6];
    const float* b_sy = (const float*)d_in[7];
    const float* w_cy = (const float*)d_in[8];
    const float* b_cy = (const float*)d_in[9];
    const float* w_t  = (const float*)d_in[10];
    const float* b_t  = (const float*)d_in[11];
    const float* w1   = (const float*)d_in[12];
    const float* b1   = (const float*)d_in[13];
    const float* w2   = (const float*)d_in[14];
    const float* b2   = (const float*)d_in[15];
    float* out = (float*)d_out;

    courier_prep<<<80, 256>>>(w1, w2);

    static bool attr_set = false;
    if (!attr_set) {
        cudaFuncSetAttribute(courier_main, cudaFuncAttributeMaxDynamicSharedMemorySize,
                             SMEM_BYTES);
        attr_set = true;
    }

    courier_main<<<4096, 256, SMEM_BYTES>>>(xy, t, w_sx, b_sx, w_cx, b_cx,
                                            w_sy, b_sy, w_cy, b_cy,
                                            w_t, b_t, b1, b2, out);
}